// round 3
// baseline (speedup 1.0000x reference)
#include <cuda_runtime.h>
#include <math.h>

#define NT     250000
#define NNODE  20000
#define NREL   64
#define RPF    8
#define EMBD   64
#define NCLS   16
#define NRP    (NNODE * RPF)          // 160000
#define NKEY   139994                 // max k = 19999*7, keys in [0, NKEY)

// ---------------- scratch (device globals; no allocation) ----------------
__device__ __align__(16) float d_l1[NT * RPF];        // 8 MB
__device__ __align__(16) float d_l2[NT * RPF];        // 8 MB
__device__ __align__(16) float d_S [NNODE * RPF];
__device__ __align__(16) float d_T [NNODE * RPF];
__device__ __align__(16) float d_colsum[NRP];
__device__ __align__(16) float d_rowsum[NRP];
__device__ __align__(16) float d_h [NNODE * EMBD];
__device__ __align__(16) float d_g [NNODE * RPF * NCLS]; // g[o, rr, c] 10 MB
__device__ __align__(16) float d_v [NT * EMBD];       // per-edge layer1 vectors, 64 MB

// CSR scratch
__device__ int d_cnt_s[NNODE],  d_off_s[NNODE + 1],  d_cur_s[NNODE];
__device__ int d_cnt_o[NNODE],  d_off_o[NNODE + 1],  d_cur_o[NNODE];
__device__ int d_cnt_k[NKEY],   d_off_k[NKEY + 1],   d_cur_k[NKEY];
__device__ int d_csr_s[NT];          // t grouped by s
__device__ int d_csr_o[NT];          // t grouped by o
__device__ int d_csr_k[NT * 7];      // (t*8+r), r>=1, grouped by k = s*r

// ---------------- K0: init ----------------
__global__ void k_init(float* __restrict__ logits, const float* __restrict__ bias2) {
    int i = blockIdx.x * blockDim.x + threadIdx.x;
    int stride = gridDim.x * blockDim.x;
    for (int j = i; j < NNODE * RPF; j += stride) { d_S[j] = 0.f; d_T[j] = 0.f; }
    for (int j = i; j < NRP; j += stride)         { d_colsum[j] = 0.f; d_rowsum[j] = 0.f; }
    for (int j = i; j < NNODE; j += stride)       { d_cnt_s[j] = 0; d_cnt_o[j] = 0; }
    for (int j = i; j < NKEY; j += stride)        d_cnt_k[j] = 0;
    for (int j = i; j < NNODE * NCLS; j += stride) logits[j] = bias2[j & 15];
}

// ---------------- K1: l1 = rm@W1+b1 ; l2 = softmax(rm@W2+b2) ; S,T sums ----
__global__ void __launch_bounds__(256) k1_edge(
    const float* __restrict__ rm, const int* __restrict__ hrow,
    const int* __restrict__ vcol,
    const float* __restrict__ W1, const float* __restrict__ b1v,
    const float* __restrict__ W2, const float* __restrict__ b2v)
{
    int warp = (blockIdx.x * blockDim.x + threadIdx.x) >> 5;
    if (warp >= (NT / 16)) return;
    int lane = threadIdx.x & 31;
    int r  = lane & 7;
    int hc = lane >> 3;

    float w1[16], w2[16];
#pragma unroll
    for (int i = 0; i < 16; i++) {
        w1[i] = __ldg(&W1[(hc * 16 + i) * 8 + r]);
        w2[i] = __ldg(&W2[(hc * 16 + i) * 8 + r]);
    }
    float bb1 = __ldg(&b1v[r]);
    float bb2 = __ldg(&b2v[r]);

    int t0 = warp * 16;
    for (int e = 0; e < 16; e++) {
        int t = t0 + e;
        const float4* row = reinterpret_cast<const float4*>(rm + (size_t)t * 64 + hc * 16);
        float p1 = 0.f, p2 = 0.f;
#pragma unroll
        for (int q = 0; q < 4; q++) {
            float4 v = __ldg(&row[q]);
            p1 += v.x * w1[4*q] + v.y * w1[4*q+1] + v.z * w1[4*q+2] + v.w * w1[4*q+3];
            p2 += v.x * w2[4*q] + v.y * w2[4*q+1] + v.z * w2[4*q+2] + v.w * w2[4*q+3];
        }
        p1 += __shfl_xor_sync(0xffffffffu, p1, 8);
        p1 += __shfl_xor_sync(0xffffffffu, p1, 16);
        p2 += __shfl_xor_sync(0xffffffffu, p2, 8);
        p2 += __shfl_xor_sync(0xffffffffu, p2, 16);

        float l1v = p1 + bb1;
        float z   = p2 + bb2;
        float m = z;
        m = fmaxf(m, __shfl_xor_sync(0xffffffffu, m, 1));
        m = fmaxf(m, __shfl_xor_sync(0xffffffffu, m, 2));
        m = fmaxf(m, __shfl_xor_sync(0xffffffffu, m, 4));
        float ev = __expf(z - m);
        float se = ev;
        se += __shfl_xor_sync(0xffffffffu, se, 1);
        se += __shfl_xor_sync(0xffffffffu, se, 2);
        se += __shfl_xor_sync(0xffffffffu, se, 4);
        float l2v = ev / se;   // relu(softmax) == softmax

        if (hc == 0) {
            int s = hrow[t];
            int o = vcol[t];
            d_l1[t * 8 + r] = l1v;
            d_l2[t * 8 + r] = l2v;
            atomicAdd(&d_S[o * 8 + r], l1v);
            atomicAdd(&d_T[s * 8 + r], l2v);
        }
    }
}

// ---------------- K2: scatter S/T into colsum/rowsum -----------------------
__global__ void __launch_bounds__(256) k2_sums() {
    __shared__ float sc, sr;
    if (threadIdx.x == 0) { sc = 0.f; sr = 0.f; }
    __syncthreads();
    int i = blockIdx.x * blockDim.x + threadIdx.x;
    if (i < NNODE * RPF) {
        int r = i & 7;
        int j = i >> 3;
        float sv = d_S[i];
        float tv = d_T[i];
        if (r == 0) { atomicAdd(&sc, sv); atomicAdd(&sr, tv); }
        else        { atomicAdd(&d_colsum[j * r], sv); atomicAdd(&d_rowsum[j * r], tv); }
    }
    __syncthreads();
    if (threadIdx.x == 0) { atomicAdd(&d_colsum[0], sc); atomicAdd(&d_rowsum[0], sr); }
}

// ---------------- CSR build: histogram -> scan -> scatter -------------------
__global__ void k_hist(const int* __restrict__ hrow, const int* __restrict__ vcol) {
    int t = blockIdx.x * blockDim.x + threadIdx.x;
    if (t >= NT) return;
    int s = hrow[t], o = vcol[t];
    atomicAdd(&d_cnt_s[s], 1);
    atomicAdd(&d_cnt_o[o], 1);
#pragma unroll
    for (int r = 1; r < 8; r++) atomicAdd(&d_cnt_k[s * r], 1);
}

// Single-block exclusive scan; grid = 3 (one block per array).
__global__ void __launch_bounds__(1024) k_scan() {
    const int* cnt; int* off; int n;
    if (blockIdx.x == 0)      { cnt = d_cnt_s; off = d_off_s; n = NNODE; }
    else if (blockIdx.x == 1) { cnt = d_cnt_o; off = d_off_o; n = NNODE; }
    else                      { cnt = d_cnt_k; off = d_off_k; n = NKEY; }

    __shared__ int wsum[32];
    __shared__ int s_carry;
    int tid = threadIdx.x, lane = tid & 31, wid = tid >> 5;
    if (tid == 0) s_carry = 0;
    __syncthreads();
    for (int base = 0; base < n; base += 1024) {
        int i = base + tid;
        int v = (i < n) ? cnt[i] : 0;
        int x = v;
#pragma unroll
        for (int d = 1; d < 32; d <<= 1) {
            int y = __shfl_up_sync(0xffffffffu, x, d);
            if (lane >= d) x += y;
        }
        if (lane == 31) wsum[wid] = x;
        __syncthreads();
        if (wid == 0) {
            int w = wsum[lane];
#pragma unroll
            for (int d = 1; d < 32; d <<= 1) {
                int y = __shfl_up_sync(0xffffffffu, w, d);
                if (lane >= d) w += y;
            }
            wsum[lane] = w;
        }
        __syncthreads();
        int incl = x + (wid > 0 ? wsum[wid - 1] : 0);
        int carry = s_carry;
        if (i < n) off[i] = carry + incl - v;
        __syncthreads();
        if (tid == 1023) s_carry = carry + incl;
        __syncthreads();
    }
    if (threadIdx.x == 0) off[n] = s_carry;
}

__global__ void k_copy_cur() {
    int i = blockIdx.x * blockDim.x + threadIdx.x;
    int stride = gridDim.x * blockDim.x;
    for (int j = i; j < NNODE; j += stride) { d_cur_s[j] = d_off_s[j]; d_cur_o[j] = d_off_o[j]; }
    for (int j = i; j < NKEY; j += stride)  d_cur_k[j] = d_off_k[j];
}

__global__ void k_scatter(const int* __restrict__ hrow, const int* __restrict__ vcol) {
    int t = blockIdx.x * blockDim.x + threadIdx.x;
    if (t >= NT) return;
    int s = hrow[t], o = vcol[t];
    int ps = atomicAdd(&d_cur_s[s], 1);  d_csr_s[ps] = t;
    int po = atomicAdd(&d_cur_o[o], 1);  d_csr_o[po] = t;
#pragma unroll
    for (int r = 1; r < 8; r++) {
        int pk = atomicAdd(&d_cur_k[s * r], 1);
        d_csr_k[pk] = t * 8 + r;
    }
}

// ---------------- K3a: per-o — v[t] = sum_r (l1/colsum)[t,r] * W1[o*r] -----
// One warp per o. Lane owns columns [2*lane, 2*lane+2). W rows in registers.
__global__ void __launch_bounds__(256) k3a_edgevec(const float* __restrict__ W)
{
    int o = (blockIdx.x * blockDim.x + threadIdx.x) >> 5;
    if (o >= NNODE) return;
    int lane = threadIdx.x & 31;

    float invc = 0.f;
    if (lane < 8) invc = 1.f / d_colsum[o * lane];

    float2 w[8];
#pragma unroll
    for (int r = 0; r < 8; r++)
        w[r] = *reinterpret_cast<const float2*>(W + (size_t)(o * r) * 64 + 2 * lane);

    int beg = d_off_o[o], end = d_off_o[o + 1];
    for (int j = beg; j < end; j++) {
        int t = d_csr_o[j];
        float av = 0.f;
        if (lane < 8) av = d_l1[t * 8 + lane] * invc;
        float ax = 0.f, ay = 0.f;
#pragma unroll
        for (int r = 0; r < 8; r++) {
            float a = __shfl_sync(0xffffffffu, av, r);
            ax += a * w[r].x;
            ay += a * w[r].y;
        }
        *reinterpret_cast<float2*>(d_v + (size_t)t * 64 + 2 * lane) = make_float2(ax, ay);
    }
}

// ---------------- K3b: per-s — h[s] = sum_{t in s} v[t]  (plain stores) -----
__global__ void __launch_bounds__(256) k3b_reduce()
{
    int s = (blockIdx.x * blockDim.x + threadIdx.x) >> 5;
    if (s >= NNODE) return;
    int lane = threadIdx.x & 31;
    float ax = 0.f, ay = 0.f;
    int beg = d_off_s[s], end = d_off_s[s + 1];
    for (int j = beg; j < end; j++) {
        int t = d_csr_s[j];
        float2 vv = *reinterpret_cast<const float2*>(d_v + (size_t)t * 64 + 2 * lane);
        ax += vv.x; ay += vv.y;
    }
    *reinterpret_cast<float2*>(d_h + (size_t)s * 64 + 2 * lane) = make_float2(ax, ay);
}

// ---------------- K4: g[node, rr, c] = relu(h+b1) @ W2cat ------------------
__global__ void __launch_bounds__(256) k4_gemm(
    const float* __restrict__ W2, const float* __restrict__ bias1)
{
    __shared__ float hs[32][129];
    __shared__ __align__(16) float ws[32][128];
    int m0 = blockIdx.x * 128;
    int tid = threadIdx.x;
    int tx = tid & 15;
    int ty = tid >> 4;

    float acc[8][8];
#pragma unroll
    for (int i = 0; i < 8; i++)
#pragma unroll
        for (int j = 0; j < 8; j++) acc[i][j] = 0.f;

    for (int kt = 0; kt < 2; kt++) {
        {
            int kk  = tid & 31;
            int nl0 = tid >> 5;
            float bv = __ldg(&bias1[kt * 32 + kk]);
#pragma unroll
            for (int it = 0; it < 16; it++) {
                int nl = nl0 + it * 8;
                int node = m0 + nl;
                float v = 0.f;
                if (node < NNODE) v = fmaxf(d_h[node * 64 + kt * 32 + kk] + bv, 0.f);
                hs[kk][nl] = v;
            }
        }
        {
            int n  = tid & 127;
            int kb = tid >> 7;
            int rr = n >> 4, c = n & 15;
#pragma unroll
            for (int it = 0; it < 16; it++) {
                int kk2 = kb + it * 2;
                ws[kk2][n] = __ldg(&W2[rr * 1024 + (kt * 32 + kk2) * 16 + c]);
            }
        }
        __syncthreads();
#pragma unroll
        for (int k = 0; k < 32; k++) {
            float av[8];
#pragma unroll
            for (int i = 0; i < 8; i++) av[i] = hs[k][tx + 16 * i];
            float4 b0 = *reinterpret_cast<const float4*>(&ws[k][ty * 8]);
            float4 b1 = *reinterpret_cast<const float4*>(&ws[k][ty * 8 + 4]);
            float bv[8] = {b0.x, b0.y, b0.z, b0.w, b1.x, b1.y, b1.z, b1.w};
#pragma unroll
            for (int i = 0; i < 8; i++)
#pragma unroll
                for (int j = 0; j < 8; j++) acc[i][j] += av[i] * bv[j];
        }
        __syncthreads();
    }
#pragma unroll
    for (int i = 0; i < 8; i++) {
        int node = m0 + tx + 16 * i;
        if (node < NNODE) {
            *reinterpret_cast<float4*>(d_g + node * 128 + ty * 8) =
                make_float4(acc[i][0], acc[i][1], acc[i][2], acc[i][3]);
            *reinterpret_cast<float4*>(d_g + node * 128 + ty * 8 + 4) =
                make_float4(acc[i][4], acc[i][5], acc[i][6], acc[i][7]);
        }
    }
}

// ---------------- K5a: r==0 entries (all map to k=0 -> logits row 0) --------
__global__ void __launch_bounds__(256) k5a_r0(
    const int* __restrict__ vcol, float* __restrict__ logits)
{
    __shared__ float sacc[16];
    if (threadIdx.x < 16) sacc[threadIdx.x] = 0.f;
    __syncthreads();

    float inv0 = 1.f / fmaxf(d_rowsum[0], 1e-6f);
    float acc[16];
#pragma unroll
    for (int c = 0; c < 16; c++) acc[c] = 0.f;

    int stride = gridDim.x * blockDim.x;
    for (int t = blockIdx.x * blockDim.x + threadIdx.x; t < NT; t += stride) {
        int o = vcol[t];
        float b = d_l2[t * 8] * inv0;
        const float4* gp = reinterpret_cast<const float4*>(d_g + (size_t)o * 128);
        float4 g0 = __ldg(&gp[0]), g1 = __ldg(&gp[1]);
        float4 g2 = __ldg(&gp[2]), g3 = __ldg(&gp[3]);
        acc[0]  += b * g0.x; acc[1]  += b * g0.y; acc[2]  += b * g0.z; acc[3]  += b * g0.w;
        acc[4]  += b * g1.x; acc[5]  += b * g1.y; acc[6]  += b * g1.z; acc[7]  += b * g1.w;
        acc[8]  += b * g2.x; acc[9]  += b * g2.y; acc[10] += b * g2.z; acc[11] += b * g2.w;
        acc[12] += b * g3.x; acc[13] += b * g3.y; acc[14] += b * g3.z; acc[15] += b * g3.w;
    }
#pragma unroll
    for (int c = 0; c < 16; c++) atomicAdd(&sacc[c], acc[c]);
    __syncthreads();
    if (threadIdx.x < 16) atomicAdd(&logits[threadIdx.x], sacc[threadIdx.x]);
}

// ---------------- K5b: per-key k (r>=1) — one half-warp per key -------------
__global__ void __launch_bounds__(256) k5b_bykey(
    const int* __restrict__ vcol, float* __restrict__ logits)
{
    int warp = (blockIdx.x * blockDim.x + threadIdx.x) >> 5;
    int lane = threadIdx.x & 31;
    int k = warp * 2 + (lane >> 4);
    int c = lane & 15;
    if (k >= NKEY) return;

    int beg = d_off_k[k], end = d_off_k[k + 1];
    if (beg == end) return;

    float inv = 1.f / fmaxf(d_rowsum[k], 1e-6f);
    int rr = k / NNODE;
    int nn = k - rr * NNODE;
    const float* gbase = d_g + rr * 16 + c;

    float acc = 0.f;
    for (int j = beg; j < end; j++) {
        int idx = d_csr_k[j];
        int t = idx >> 3;
        int o = vcol[t];
        float b = d_l2[idx] * inv;
        acc += b * __ldg(gbase + (size_t)o * 128);
    }
    atomicAdd(&logits[nn * 16 + c], acc);
}

// ---------------- launch ----------------------------------------------------
extern "C" void kernel_launch(void* const* d_in, const int* in_sizes, int n_in,
                              void* d_out, int out_size) {
    const float* rm    = (const float*)d_in[0];
    const int*   hrow  = (const int*)  d_in[1];
    const int*   vcol  = (const int*)  d_in[4];
    const float* W_l1  = (const float*)d_in[5];
    const float* b_l1  = (const float*)d_in[6];
    const float* W_l2  = (const float*)d_in[7];
    const float* b_l2  = (const float*)d_in[8];
    const float* wts1  = (const float*)d_in[9];
    const float* wts2  = (const float*)d_in[10];
    const float* bias1 = (const float*)d_in[11];
    const float* bias2 = (const float*)d_in[12];
    float* logits = (float*)d_out;

    k_init<<<1280, 256>>>(logits, bias2);
    k1_edge<<<(NT / 16 * 32 + 255) / 256, 256>>>(rm, hrow, vcol, W_l1, b_l1, W_l2, b_l2);
    k2_sums<<<(NNODE * RPF + 255) / 256, 256>>>();
    k_hist<<<(NT + 255) / 256, 256>>>(hrow, vcol);
    k_scan<<<3, 1024>>>();
    k_copy_cur<<<640, 256>>>();
    k_scatter<<<(NT + 255) / 256, 256>>>(hrow, vcol);
    k3a_edgevec<<<(NNODE * 32 + 255) / 256, 256>>>(wts1);
    k3b_reduce<<<(NNODE * 32 + 255) / 256, 256>>>();
    k4_gemm<<<(NNODE + 127) / 128, 256>>>(wts2, bias1);
    k5a_r0<<<296, 256>>>(vcol, logits);
    k5b_bykey<<<((NKEY + 1) / 2 * 32 + 255) / 256, 256>>>(vcol, logits);
}

// round 4
// speedup vs baseline: 2.0582x; 2.0582x over previous
#include <cuda_runtime.h>
#include <math.h>

#define NT     250000
#define NNODE  20000
#define NREL   64
#define RPF    8
#define EMBD   64
#define NCLS   16
#define NRP    (NNODE * RPF)          // 160000

// ---------------- scratch (device globals; no allocation) ----------------
__device__ __align__(16) float d_l1[NT * RPF];        // 8 MB
__device__ __align__(16) float d_l2[NT * RPF];        // 8 MB
__device__ __align__(16) float d_colsum[NRP];
__device__ __align__(16) float d_rowsum[NRP];
__device__ __align__(16) float d_h [NNODE * EMBD];    // 5 MB
__device__ __align__(16) float d_g [NNODE * RPF * NCLS]; // 10 MB, L2-resident

// CSR scratch (s- and o-grouped only; no k-CSR)
__device__ int d_cnt_s[NNODE], d_off_s[NNODE + 1], d_cur_s[NNODE];
__device__ int d_cnt_o[NNODE], d_off_o[NNODE + 1], d_cur_o[NNODE];
__device__ int d_csr_s_t[NT], d_csr_s_o[NT];   // edges grouped by s; payload t and o
__device__ int d_csr_o_t[NT], d_csr_o_s[NT];   // edges grouped by o; payload t and s

__device__ __forceinline__ void red_add_v4(float* addr, float a, float b, float c, float d) {
    asm volatile("red.global.v4.f32.add [%0], {%1, %2, %3, %4};"
                 :: "l"(addr), "f"(a), "f"(b), "f"(c), "f"(d) : "memory");
}

// ---------------- K0: init ----------------
__global__ void k_init(float* __restrict__ logits, const float* __restrict__ bias2) {
    int i = blockIdx.x * blockDim.x + threadIdx.x;
    int stride = gridDim.x * blockDim.x;
    for (int j = i; j < NRP; j += stride)          { d_colsum[j] = 0.f; d_rowsum[j] = 0.f; }
    for (int j = i; j < NNODE; j += stride)        { d_cnt_s[j] = 0; d_cnt_o[j] = 0; }
    for (int j = i; j < NNODE * EMBD; j += stride) d_h[j] = 0.f;
    for (int j = i; j < NNODE * NCLS; j += stride) logits[j] = bias2[j & 15];
}

// ---------------- CSR build --------------------------------------------------
__global__ void k_hist(const int* __restrict__ hrow, const int* __restrict__ vcol) {
    int t = blockIdx.x * blockDim.x + threadIdx.x;
    if (t >= NT) return;
    atomicAdd(&d_cnt_s[hrow[t]], 1);
    atomicAdd(&d_cnt_o[vcol[t]], 1);
}

// grid = 2: block 0 scans cnt_s -> off_s/cur_s, block 1 scans cnt_o.
__global__ void __launch_bounds__(1024) k_scan() {
    const int* cnt = (blockIdx.x == 0) ? d_cnt_s : d_cnt_o;
    int* off       = (blockIdx.x == 0) ? d_off_s : d_off_o;
    int* cur       = (blockIdx.x == 0) ? d_cur_s : d_cur_o;
    const int n = NNODE;

    __shared__ int wsum[32];
    __shared__ int s_carry;
    int tid = threadIdx.x, lane = tid & 31, wid = tid >> 5;
    if (tid == 0) s_carry = 0;
    __syncthreads();
    for (int base = 0; base < n; base += 1024) {
        int i = base + tid;
        int v = (i < n) ? cnt[i] : 0;
        int x = v;
#pragma unroll
        for (int d = 1; d < 32; d <<= 1) {
            int y = __shfl_up_sync(0xffffffffu, x, d);
            if (lane >= d) x += y;
        }
        if (lane == 31) wsum[wid] = x;
        __syncthreads();
        if (wid == 0) {
            int w = wsum[lane];
#pragma unroll
            for (int d = 1; d < 32; d <<= 1) {
                int y = __shfl_up_sync(0xffffffffu, w, d);
                if (lane >= d) w += y;
            }
            wsum[lane] = w;
        }
        __syncthreads();
        int incl = x + (wid > 0 ? wsum[wid - 1] : 0);
        int carry = s_carry;
        if (i < n) { int e = carry + incl - v; off[i] = e; cur[i] = e; }
        __syncthreads();
        if (tid == 1023) s_carry = carry + incl;
        __syncthreads();
    }
    if (threadIdx.x == 0) off[n] = s_carry;
}

__global__ void k_scatter(const int* __restrict__ hrow, const int* __restrict__ vcol) {
    int t = blockIdx.x * blockDim.x + threadIdx.x;
    if (t >= NT) return;
    int s = hrow[t], o = vcol[t];
    int ps = atomicAdd(&d_cur_s[s], 1);
    d_csr_s_t[ps] = t;  d_csr_s_o[ps] = o;
    int po = atomicAdd(&d_cur_o[o], 1);
    d_csr_o_t[po] = t;  d_csr_o_s[po] = s;
}

// ---------------- K1: l1 = rm@W1+b1 ; l2 = softmax(rm@W2+b2)  (no atomics) --
__global__ void __launch_bounds__(256) k1_edge(
    const float* __restrict__ rm,
    const float* __restrict__ W1, const float* __restrict__ b1v,
    const float* __restrict__ W2, const float* __restrict__ b2v)
{
    int warp = (blockIdx.x * blockDim.x + threadIdx.x) >> 5;
    if (warp >= (NT / 16)) return;
    int lane = threadIdx.x & 31;
    int r  = lane & 7;
    int hc = lane >> 3;

    float w1[16], w2[16];
#pragma unroll
    for (int i = 0; i < 16; i++) {
        w1[i] = __ldg(&W1[(hc * 16 + i) * 8 + r]);
        w2[i] = __ldg(&W2[(hc * 16 + i) * 8 + r]);
    }
    float bb1 = __ldg(&b1v[r]);
    float bb2 = __ldg(&b2v[r]);

    int t0 = warp * 16;
    for (int e = 0; e < 16; e++) {
        int t = t0 + e;
        const float4* row = reinterpret_cast<const float4*>(rm + (size_t)t * 64 + hc * 16);
        float p1 = 0.f, p2 = 0.f;
#pragma unroll
        for (int q = 0; q < 4; q++) {
            float4 v = __ldg(&row[q]);
            p1 += v.x * w1[4*q] + v.y * w1[4*q+1] + v.z * w1[4*q+2] + v.w * w1[4*q+3];
            p2 += v.x * w2[4*q] + v.y * w2[4*q+1] + v.z * w2[4*q+2] + v.w * w2[4*q+3];
        }
        p1 += __shfl_xor_sync(0xffffffffu, p1, 8);
        p1 += __shfl_xor_sync(0xffffffffu, p1, 16);
        p2 += __shfl_xor_sync(0xffffffffu, p2, 8);
        p2 += __shfl_xor_sync(0xffffffffu, p2, 16);

        float l1v = p1 + bb1;
        float z   = p2 + bb2;
        float m = z;
        m = fmaxf(m, __shfl_xor_sync(0xffffffffu, m, 1));
        m = fmaxf(m, __shfl_xor_sync(0xffffffffu, m, 2));
        m = fmaxf(m, __shfl_xor_sync(0xffffffffu, m, 4));
        float ev = __expf(z - m);
        float se = ev;
        se += __shfl_xor_sync(0xffffffffu, se, 1);
        se += __shfl_xor_sync(0xffffffffu, se, 2);
        se += __shfl_xor_sync(0xffffffffu, se, 4);
        float l2v = ev / se;   // relu(softmax) == softmax

        if (hc == 0) {
            d_l1[t * 8 + r] = l1v;
            d_l2[t * 8 + r] = l2v;
        }
    }
}

// ---------------- K2: colsum/rowsum via CSR (8-lane subgroup per node) ------
// sub < NNODE: colsum from l1 over o-group; else rowsum from l2 over s-group.
__global__ void __launch_bounds__(256) k2_sums() {
    __shared__ float sc, sr;
    if (threadIdx.x == 0) { sc = 0.f; sr = 0.f; }
    __syncthreads();

    int sub = (blockIdx.x * blockDim.x + threadIdx.x) >> 3;
    int r = threadIdx.x & 7;
    if (sub < NNODE) {
        int o = sub;
        int beg = d_off_o[o], end = d_off_o[o + 1];
        float S = 0.f;
        for (int j = beg; j < end; j++) {
            int t = d_csr_o_t[j];
            S += d_l1[t * 8 + r];
        }
        if (r == 0) atomicAdd(&sc, S);
        else        atomicAdd(&d_colsum[o * r], S);
    } else if (sub < 2 * NNODE) {
        int s = sub - NNODE;
        int beg = d_off_s[s], end = d_off_s[s + 1];
        float S = 0.f;
        for (int j = beg; j < end; j++) {
            int t = d_csr_s_t[j];
            S += d_l2[t * 8 + r];
        }
        if (r == 0) atomicAdd(&sr, S);
        else        atomicAdd(&d_rowsum[s * r], S);
    }
    __syncthreads();
    if (threadIdx.x == 0) {
        atomicAdd(&d_colsum[0], sc);
        atomicAdd(&d_rowsum[0], sr);
    }
}

// ---------------- K3: warp per o; W1 rows in regs; red.v4 into h ------------
// 16-lane halves process 2 edges per iteration. Lane (lane&15) owns cols
// [4q, 4q+4) with q = lane&15.
__global__ void __launch_bounds__(256) k3_layer1(const float* __restrict__ W)
{
    int o = (blockIdx.x * blockDim.x + threadIdx.x) >> 5;
    if (o >= NNODE) return;
    int lane = threadIdx.x & 31;
    int q = lane & 15;
    int half = lane >> 4;

    float invc = 1.f / d_colsum[o * (lane & 7)];   // valid on all lanes (r = lane&7)

    float4 w[8];
#pragma unroll
    for (int r = 0; r < 8; r++)
        w[r] = __ldg(reinterpret_cast<const float4*>(W + (size_t)(o * r) * 64 + 4 * q));

    int beg = d_off_o[o], end = d_off_o[o + 1];
    for (int j = beg; j < end; j += 2) {
        int jj = j + half;
        bool act = (jj < end);
        int jl = act ? jj : (end - 1);           // end > beg here, safe
        int t = d_csr_o_t[jl];
        int s = d_csr_o_s[jl];
        float av = 0.f;
        if (q < 8) av = d_l1[t * 8 + (lane & 7)] * invc;

        float ax = 0.f, ay = 0.f, az = 0.f, aw = 0.f;
#pragma unroll
        for (int r = 0; r < 8; r++) {
            float a = __shfl_sync(0xffffffffu, av, (lane & 16) + r);
            ax += a * w[r].x; ay += a * w[r].y; az += a * w[r].z; aw += a * w[r].w;
        }
        if (act) red_add_v4(d_h + (size_t)s * 64 + 4 * q, ax, ay, az, aw);
    }
}

// ---------------- K4: g[node, rr, c] = relu(h+b1) @ W2cat ------------------
__global__ void __launch_bounds__(256) k4_gemm(
    const float* __restrict__ W2, const float* __restrict__ bias1)
{
    __shared__ float hs[32][129];
    __shared__ __align__(16) float ws[32][128];
    int m0 = blockIdx.x * 128;
    int tid = threadIdx.x;
    int tx = tid & 15;
    int ty = tid >> 4;

    float acc[8][8];
#pragma unroll
    for (int i = 0; i < 8; i++)
#pragma unroll
        for (int j = 0; j < 8; j++) acc[i][j] = 0.f;

    for (int kt = 0; kt < 2; kt++) {
        {
            int kk  = tid & 31;
            int nl0 = tid >> 5;
            float bv = __ldg(&bias1[kt * 32 + kk]);
#pragma unroll
            for (int it = 0; it < 16; it++) {
                int nl = nl0 + it * 8;
                int node = m0 + nl;
                float v = 0.f;
                if (node < NNODE) v = fmaxf(d_h[node * 64 + kt * 32 + kk] + bv, 0.f);
                hs[kk][nl] = v;
            }
        }
        {
            int n  = tid & 127;
            int kb = tid >> 7;
            int rr = n >> 4, c = n & 15;
#pragma unroll
            for (int it = 0; it < 16; it++) {
                int kk2 = kb + it * 2;
                ws[kk2][n] = __ldg(&W2[rr * 1024 + (kt * 32 + kk2) * 16 + c]);
            }
        }
        __syncthreads();
#pragma unroll
        for (int k = 0; k < 32; k++) {
            float av[8];
#pragma unroll
            for (int i = 0; i < 8; i++) av[i] = hs[k][tx + 16 * i];
            float4 b0 = *reinterpret_cast<const float4*>(&ws[k][ty * 8]);
            float4 b1 = *reinterpret_cast<const float4*>(&ws[k][ty * 8 + 4]);
            float bv[8] = {b0.x, b0.y, b0.z, b0.w, b1.x, b1.y, b1.z, b1.w};
#pragma unroll
            for (int i = 0; i < 8; i++)
#pragma unroll
                for (int j = 0; j < 8; j++) acc[i][j] += av[i] * bv[j];
        }
        __syncthreads();
    }
#pragma unroll
    for (int i = 0; i < 8; i++) {
        int node = m0 + tx + 16 * i;
        if (node < NNODE) {
            *reinterpret_cast<float4*>(d_g + node * 128 + ty * 8) =
                make_float4(acc[i][0], acc[i][1], acc[i][2], acc[i][3]);
            *reinterpret_cast<float4*>(d_g + node * 128 + ty * 8 + 4) =
                make_float4(acc[i][4], acc[i][5], acc[i][6], acc[i][7]);
        }
    }
}

// ---------------- K5: warp per s; keys k = s*r, r=0..7 ----------------------
// Lane = (half, c): half 0 handles r in {0,2,4,6}, half 1 r in {1,3,5,7}.
// acc[j] accumulated in registers over the s-group; one atomic per (r,c) at end.
// r==0 (k=0 -> logits row 0, shared by ALL s) goes through block smem reduction.
__global__ void __launch_bounds__(256) k5_layer2(float* __restrict__ logits)
{
    __shared__ float sacc[16];
    if (threadIdx.x < 16) sacc[threadIdx.x] = 0.f;
    __syncthreads();

    int s = (blockIdx.x * blockDim.x + threadIdx.x) >> 5;   // exactly NNODE warps
    int lane = threadIdx.x & 31;
    int half = lane >> 4;
    int c = lane & 15;

    float inv[4]; int rrv[4], nnv[4];
#pragma unroll
    for (int j = 0; j < 4; j++) {
        int r = 2 * j + half;
        int k = s * r;
        inv[j] = 1.f / fmaxf(d_rowsum[k], 1e-6f);
        rrv[j] = k / NNODE;
        nnv[j] = k - rrv[j] * NNODE;
    }

    float acc[4] = {0.f, 0.f, 0.f, 0.f};
    int beg = d_off_s[s], end = d_off_s[s + 1];
    for (int j = beg; j < end; j++) {
        int t = d_csr_s_t[j];
        int o = d_csr_s_o[j];
        float l2v = 0.f;
        if (lane < 8) l2v = d_l2[t * 8 + lane];
        const float* gb = d_g + (size_t)o * 128 + c;
#pragma unroll
        for (int jj = 0; jj < 4; jj++) {
            float a = __shfl_sync(0xffffffffu, l2v, 2 * jj + half);
            acc[jj] += a * __ldg(gb + rrv[jj] * 16);
        }
    }
#pragma unroll
    for (int j = 0; j < 4; j++) {
        int r = 2 * j + half;
        float v = acc[j] * inv[j];
        if (r == 0)      atomicAdd(&sacc[c], v);             // k==0 hotspot
        else             atomicAdd(&logits[nnv[j] * 16 + c], v);
    }
    __syncthreads();
    if (threadIdx.x < 16) atomicAdd(&logits[threadIdx.x], sacc[threadIdx.x]);
}

// ---------------- launch ----------------------------------------------------
extern "C" void kernel_launch(void* const* d_in, const int* in_sizes, int n_in,
                              void* d_out, int out_size) {
    const float* rm    = (const float*)d_in[0];
    const int*   hrow  = (const int*)  d_in[1];
    const int*   vcol  = (const int*)  d_in[4];
    const float* W_l1  = (const float*)d_in[5];
    const float* b_l1  = (const float*)d_in[6];
    const float* W_l2  = (const float*)d_in[7];
    const float* b_l2  = (const float*)d_in[8];
    const float* wts1  = (const float*)d_in[9];
    const float* wts2  = (const float*)d_in[10];
    const float* bias1 = (const float*)d_in[11];
    const float* bias2 = (const float*)d_in[12];
    float* logits = (float*)d_out;

    k_init<<<1280, 256>>>(logits, bias2);
    k_hist<<<(NT + 255) / 256, 256>>>(hrow, vcol);
    k_scan<<<2, 1024>>>();
    k_scatter<<<(NT + 255) / 256, 256>>>(hrow, vcol);
    k1_edge<<<(NT / 16 * 32 + 255) / 256, 256>>>(rm, W_l1, b_l1, W_l2, b_l2);
    k2_sums<<<(2 * NNODE * 8 + 255) / 256, 256>>>();
    k3_layer1<<<(NNODE * 32 + 255) / 256, 256>>>(wts1);
    k4_gemm<<<(NNODE + 127) / 128, 256>>>(wts2, bias1);
    k5_layer2<<<(NNODE * 32 + 255) / 256, 256>>>(logits);
}